// round 13
// baseline (speedup 1.0000x reference)
#include <cuda_runtime.h>
#include <cuda_bf16.h>
#include <math.h>
#include <stdint.h>

#define EMB   128
#define NUv   100000
#define NVv   50000
#define NEv   500000

#define WP_STRIDE  264  // words per (kt,tig) W pair-row (paired b0,b1) -> LDS.64 B-frags
#define XS_STRIDE  132  // words per X row (K=128) -> conflict-free A-frag LDS
#define XS2_STRIDE 260  // words per X row (K=256) for merge

#define GRID_MMA   296  // 2 blocks/SM * 148 SMs (persistent-tile)
#define GRID_MERGE 148

// ---------------- scratch (device globals: allocation-guard-safe) ----------
__device__ float g_vt[(size_t)NUv * EMB];
__device__ float g_et[(size_t)NEv * EMB];
__device__ float g_ct[(size_t)NVv * EMB];
__device__ float g_agg[(size_t)NUv * EMB];

// ---------------- helpers ----------------
__device__ __forceinline__ uint32_t f2tf(float x) {
    uint32_t r;
    asm("cvt.rna.tf32.f32 %0, %1;" : "=r"(r) : "f"(x));
    return r;
}

__device__ __forceinline__ void pf_l2(const void* p) {
    asm volatile("prefetch.global.L2 [%0];" :: "l"(p));
}

__device__ __forceinline__ void mma8(float& c0, float& c1, float& c2, float& c3,
                                     uint32_t a0, uint32_t a1, uint32_t a2, uint32_t a3,
                                     uint32_t b0, uint32_t b1)
{
    asm volatile(
        "mma.sync.aligned.m16n8k8.row.col.f32.tf32.tf32.f32 "
        "{%0,%1,%2,%3}, {%4,%5,%6,%7}, {%8,%9}, {%0,%1,%2,%3};"
        : "+f"(c0), "+f"(c1), "+f"(c2), "+f"(c3)
        : "r"(a0), "r"(a1), "r"(a2), "r"(a3), "r"(b0), "r"(b1));
}

__device__ __forceinline__ void red_v4(float* p, float v0, float v1, float v2, float v3)
{
    asm volatile("red.global.add.v4.f32 [%0], {%1,%2,%3,%4};"
                 :: "l"(p), "f"(v0), "f"(v1), "f"(v2), "f"(v3) : "memory");
}

// Vectorized staging of W[KD][128] ([k][n]) into paired-tf32 smem:
//   Wp[(kt*4+tig)*WP_STRIDE + 2*n + half], k = kt*8 + half*4 + tig
template<int KD>
__device__ __forceinline__ void stage_W_tf32(const float* __restrict__ W,
                                             uint32_t* __restrict__ Wp,
                                             int tid, int nthreads)
{
    #pragma unroll 2
    for (int i = tid; i < (KD / 2) * 32; i += nthreads) {
        const int pr = i >> 5;
        const int c4 = i & 31;
        const int kt = pr >> 2, tig = pr & 3;
        const int k0 = kt * 8 + tig;
        const float4 w0 = ((const float4*)(W + (size_t)k0 * EMB))[c4];
        const float4 w1 = ((const float4*)(W + (size_t)(k0 + 4) * EMB))[c4];
        uint32_t* dst = Wp + pr * WP_STRIDE + 8 * c4;
        uint4 lo, hi;
        lo.x = f2tf(w0.x); lo.y = f2tf(w1.x); lo.z = f2tf(w0.y); lo.w = f2tf(w1.y);
        hi.x = f2tf(w0.z); hi.y = f2tf(w1.z); hi.z = f2tf(w0.w); hi.w = f2tf(w1.w);
        ((uint4*)dst)[0] = lo;
        ((uint4*)dst)[1] = hi;
    }
}

// 16-row x 64-col warp mainloop (ln_gemm / merge)
template<int NKT, int XSTR>
__device__ __forceinline__ void mma_mainloop_half(const uint32_t* __restrict__ Xs,
                                                  const uint32_t* __restrict__ Wp,
                                                  int r0, int gq, int tig, int ch,
                                                  float acc[8][4])
{
    #pragma unroll
    for (int kt = 0; kt < NKT; ++kt) {
        const uint32_t* xl = Xs + (r0 + gq) * XSTR + kt * 8;
        const uint32_t* xh = Xs + (r0 + gq + 8) * XSTR + kt * 8;
        const uint32_t a0 = xl[tig];
        const uint32_t a1 = xh[tig];
        const uint32_t a2 = xl[tig + 4];
        const uint32_t a3 = xh[tig + 4];
        const uint32_t* wrow = Wp + (kt * 4 + tig) * WP_STRIDE + 2 * (ch * 64);
        uint2 bfr[8];
        #pragma unroll
        for (int nt = 0; nt < 8; ++nt)
            bfr[nt] = *(const uint2*)(wrow + 2 * (nt * 8 + gq));
        #pragma unroll
        for (int nt = 0; nt < 8; ++nt)
            mma8(acc[nt][0], acc[nt][1], acc[nt][2], acc[nt][3],
                 a0, a1, a2, a3, bfr[nt].x, bfr[nt].y);
    }
}

// =====================================================================
// Kernel 1 (tf32, persistent): Y[row] = LN(X[row]; g,b) @ W (+bias)
// =====================================================================
__global__ __launch_bounds__(256, 2)
void ln_gemm_tf32(const float* __restrict__ X, const float* __restrict__ W,
                  const float* __restrict__ bias,
                  const float* __restrict__ g, const float* __restrict__ b,
                  float* __restrict__ Y, int N, int stream_out)
{
    extern __shared__ uint32_t smu[];
    uint32_t* Wp = smu;
    uint32_t* Xs = smu + 64 * WP_STRIDE;
    float*    Xf = (float*)Xs;

    const int tid  = threadIdx.x;
    const int lane = tid & 31;
    const int warp = tid >> 5;
    const int gq   = lane >> 2;
    const int tig  = lane & 3;
    const int r0   = (warp >> 1) * 16;
    const int ch   = warp & 1;
    const int pr_r = lane >> 2;   // prefetch: row within warp's 8
    const int pr_l = lane & 3;    // prefetch: 128B line within row

    stage_W_tf32<128>(W, Wp, tid, 256);

    const float4 gv = ((const float4*)g)[lane];
    const float4 bv = ((const float4*)b)[lane];
    float4 bb = make_float4(0.f, 0.f, 0.f, 0.f);
    if (bias) bb = ((const float4*)bias)[lane];

    const int nTiles = (N + 63) >> 6;
    for (int tile = blockIdx.x; tile < nTiles; tile += gridDim.x) {
        const int row0 = tile * 64;
        __syncthreads();

        #pragma unroll
        for (int r = 0; r < 8; ++r) {
            const int lr  = warp * 8 + r;
            const int row = row0 + lr;
            float4 xv = make_float4(0.f, 0.f, 0.f, 0.f);
            if (row < N) xv = __ldcs(((const float4*)(X + (size_t)row * EMB)) + lane);
            float s  = xv.x + xv.y + xv.z + xv.w;
            float ss = xv.x * xv.x + xv.y * xv.y + xv.z * xv.z + xv.w * xv.w;
            #pragma unroll
            for (int o = 16; o; o >>= 1) {
                s  += __shfl_xor_sync(0xffffffffu, s,  o);
                ss += __shfl_xor_sync(0xffffffffu, ss, o);
            }
            const float mu   = s * (1.f / EMB);
            const float rstd = rsqrtf(ss * (1.f / EMB) - mu * mu + 1e-5f);
            uint4 q;
            q.x = f2tf((xv.x - mu) * rstd * gv.x + bv.x);
            q.y = f2tf((xv.y - mu) * rstd * gv.y + bv.y);
            q.z = f2tf((xv.z - mu) * rstd * gv.z + bv.z);
            q.w = f2tf((xv.w - mu) * rstd * gv.w + bv.w);
            *(uint4*)(Xs + lr * XS_STRIDE + lane * 4) = q;
        }
        __syncthreads();

        // prefetch next tile's rows into L2 (hidden under the mainloop)
        {
            const int rown = (tile + gridDim.x) * 64 + warp * 8 + pr_r;
            if (tile + gridDim.x < nTiles && rown < N)
                pf_l2(X + (size_t)rown * EMB + pr_l * 32);
        }

        float acc[8][4];
        #pragma unroll
        for (int i = 0; i < 8; ++i)
            #pragma unroll
            for (int j = 0; j < 4; ++j) acc[i][j] = 0.f;

        mma_mainloop_half<16, XS_STRIDE>(Xs, Wp, r0, gq, tig, ch, acc);

        __syncthreads();
        #pragma unroll
        for (int nt = 0; nt < 8; ++nt) {
            const int col = ch * 64 + nt * 8 + 2 * tig;
            float* rl = Xf + (r0 + gq)     * XS_STRIDE + col;
            float* rh = Xf + (r0 + gq + 8) * XS_STRIDE + col;
            rl[0] = acc[nt][0]; rl[1] = acc[nt][1];
            rh[0] = acc[nt][2]; rh[1] = acc[nt][3];
        }
        __syncthreads();

        #pragma unroll
        for (int r = 0; r < 8; ++r) {
            const int lr  = warp * 8 + r;
            const int row = row0 + lr;
            if (row < N) {
                float4 o = ((const float4*)(Xf + lr * XS_STRIDE))[lane];
                o.x += bb.x; o.y += bb.y; o.z += bb.z; o.w += bb.w;
                if (stream_out) __stcs(((float4*)(Y + (size_t)row * EMB)) + lane, o);
                else            ((float4*)(Y + (size_t)row * EMB))[lane] = o;
            }
        }
    }
}

// =====================================================================
// Kernel 2 (tf32, persistent): fused edge join + LN + GEMM + LN + red.v4
// Warp tiling 32x32; next-tile gather rows prefetched into L2 under mainloop.
// =====================================================================
__global__ __launch_bounds__(256, 2)
void edge_join_tf32(const float* __restrict__ vt, const float* __restrict__ et,
                    const float* __restrict__ ct,
                    const int* __restrict__ e_u, const int* __restrict__ e_v,
                    const float* __restrict__ Wj, const float* __restrict__ bj,
                    const float* __restrict__ g1, const float* __restrict__ b1,
                    const float* __restrict__ g2, const float* __restrict__ b2,
                    float* __restrict__ agg, int seg_by_ev, int NE)
{
    extern __shared__ uint32_t smu[];
    uint32_t* Wp = smu;
    uint32_t* Xs = smu + 64 * WP_STRIDE;
    __shared__ int   segs[64];
    __shared__ float sP[64][4], ssP[64][4];

    const int tid  = threadIdx.x;
    const int lane = tid & 31;
    const int warp = tid >> 5;
    const int gq   = lane >> 2;
    const int tig  = lane & 3;
    const int wr   = warp >> 2;        // 0-1: row half (32 rows)
    const int wc   = warp & 3;         // 0-3: col quarter (32 cols)
    const int rbase = wr * 32;
    const int cbase = wc * 32;
    const bool odd  = (tig & 1);
    const int pr_r  = lane >> 2;
    const int pr_l  = lane & 3;

    stage_W_tf32<128>(Wj, Wp, tid, 256);

    const float4 g1v = ((const float4*)g1)[lane];
    const float4 b1v = ((const float4*)b1)[lane];

    const int nTiles = (NE + 63) >> 6;
    for (int tile = blockIdx.x; tile < nTiles; tile += gridDim.x) {
        const int e0 = tile * 64;
        __syncthreads();

        // ---- stage: warp stages rows warp*8..+8 ----
        int iu[8], iv[8];
        #pragma unroll
        for (int r = 0; r < 8; ++r) {
            const int e = e0 + warp * 8 + r;
            iu[r] = (e < NE) ? __ldg(e_u + e) : -1;
            iv[r] = (e < NE) ? __ldg(e_v + e) : -1;
        }
        if (lane == 0) {
            #pragma unroll
            for (int r = 0; r < 8; ++r)
                segs[warp * 8 + r] = (iu[r] < 0) ? -1 : (seg_by_ev ? iv[r] : iu[r]);
        }

        #pragma unroll
        for (int r = 0; r < 8; ++r) {
            const int lr = warp * 8 + r;
            const int e  = e0 + lr;
            float4 xv = make_float4(0.f, 0.f, 0.f, 0.f);
            if (iu[r] >= 0) {
                const float4 m = __ldcs(((const float4*)(et + (size_t)e * EMB)) + lane);
                const float4 a = ((const float4*)(vt + (size_t)iu[r] * EMB))[lane];
                const float4 c = ((const float4*)(ct + (size_t)iv[r] * EMB))[lane];
                xv.x = fmaxf(a.x + m.x + c.x, 0.f);
                xv.y = fmaxf(a.y + m.y + c.y, 0.f);
                xv.z = fmaxf(a.z + m.z + c.z, 0.f);
                xv.w = fmaxf(a.w + m.w + c.w, 0.f);
            }
            float s  = xv.x + xv.y + xv.z + xv.w;
            float ss = xv.x * xv.x + xv.y * xv.y + xv.z * xv.z + xv.w * xv.w;
            #pragma unroll
            for (int o = 16; o; o >>= 1) {
                s  += __shfl_xor_sync(0xffffffffu, s,  o);
                ss += __shfl_xor_sync(0xffffffffu, ss, o);
            }
            const float mu   = s * (1.f / EMB);
            const float rstd = rsqrtf(ss * (1.f / EMB) - mu * mu + 1e-5f);
            uint4 q;
            q.x = f2tf((xv.x - mu) * rstd * g1v.x + b1v.x);
            q.y = f2tf((xv.y - mu) * rstd * g1v.y + b1v.y);
            q.z = f2tf((xv.z - mu) * rstd * g1v.z + b1v.z);
            q.w = f2tf((xv.w - mu) * rstd * g1v.w + b1v.w);
            *(uint4*)(Xs + lr * XS_STRIDE + lane * 4) = q;
        }
        __syncthreads();

        // ---- prefetch next tile's gather rows into L2 (under mainloop) ----
        {
            const int tn = tile + gridDim.x;
            const int en = tn * 64 + warp * 8 + pr_r;
            if (tn < nTiles && en < NE) {
                const int iun = __ldg(e_u + en);
                const int ivn = __ldg(e_v + en);
                pf_l2(vt + (size_t)iun * EMB + pr_l * 32);
                pf_l2(ct + (size_t)ivn * EMB + pr_l * 32);
                pf_l2(et + (size_t)en  * EMB + pr_l * 32);
            }
        }

        // ---- mainloop: 2 rowgroups x 4 nt, B-frags shared across rowgroups
        float acc[2][4][4];
        #pragma unroll
        for (int rg = 0; rg < 2; ++rg)
            #pragma unroll
            for (int nt = 0; nt < 4; ++nt)
                #pragma unroll
                for (int j = 0; j < 4; ++j) acc[rg][nt][j] = 0.f;

        #pragma unroll
        for (int kt = 0; kt < 16; ++kt) {
            uint32_t a[2][4];
            #pragma unroll
            for (int rg = 0; rg < 2; ++rg) {
                const uint32_t* xl = Xs + (rbase + rg * 16 + gq) * XS_STRIDE + kt * 8;
                const uint32_t* xh = Xs + (rbase + rg * 16 + gq + 8) * XS_STRIDE + kt * 8;
                a[rg][0] = xl[tig];
                a[rg][1] = xh[tig];
                a[rg][2] = xl[tig + 4];
                a[rg][3] = xh[tig + 4];
            }
            const uint32_t* wrow = Wp + (kt * 4 + tig) * WP_STRIDE + 2 * cbase;
            uint2 bfr[4];
            #pragma unroll
            for (int nt = 0; nt < 4; ++nt)
                bfr[nt] = *(const uint2*)(wrow + 2 * (nt * 8 + gq));
            #pragma unroll
            for (int rg = 0; rg < 2; ++rg)
                #pragma unroll
                for (int nt = 0; nt < 4; ++nt)
                    mma8(acc[rg][nt][0], acc[rg][nt][1], acc[rg][nt][2], acc[rg][nt][3],
                         a[rg][0], a[rg][1], a[rg][2], a[rg][3], bfr[nt].x, bfr[nt].y);
        }

        // ---- epilogue: +bias, per-row partial stats (32-col partials) ----
        float sl[2] = {0.f, 0.f}, ssl[2] = {0.f, 0.f};
        float sh[2] = {0.f, 0.f}, ssh[2] = {0.f, 0.f};
        #pragma unroll
        for (int rg = 0; rg < 2; ++rg)
            #pragma unroll
            for (int nt = 0; nt < 4; ++nt) {
                const int col = cbase + nt * 8 + 2 * tig;
                const float2 bjv = *(const float2*)(bj + col);
                acc[rg][nt][0] += bjv.x; acc[rg][nt][1] += bjv.y;
                acc[rg][nt][2] += bjv.x; acc[rg][nt][3] += bjv.y;
                sl[rg]  += acc[rg][nt][0] + acc[rg][nt][1];
                ssl[rg] += acc[rg][nt][0] * acc[rg][nt][0] + acc[rg][nt][1] * acc[rg][nt][1];
                sh[rg]  += acc[rg][nt][2] + acc[rg][nt][3];
                ssh[rg] += acc[rg][nt][2] * acc[rg][nt][2] + acc[rg][nt][3] * acc[rg][nt][3];
            }
        #pragma unroll
        for (int o = 1; o < 4; o <<= 1) {
            #pragma unroll
            for (int rg = 0; rg < 2; ++rg) {
                sl[rg]  += __shfl_xor_sync(0xffffffffu, sl[rg],  o);
                ssl[rg] += __shfl_xor_sync(0xffffffffu, ssl[rg], o);
                sh[rg]  += __shfl_xor_sync(0xffffffffu, sh[rg],  o);
                ssh[rg] += __shfl_xor_sync(0xffffffffu, ssh[rg], o);
            }
        }
        if (tig == 0) {
            #pragma unroll
            for (int rg = 0; rg < 2; ++rg) {
                sP [rbase + rg * 16 + gq][wc]     = sl[rg];
                ssP[rbase + rg * 16 + gq][wc]     = ssl[rg];
                sP [rbase + rg * 16 + gq + 8][wc] = sh[rg];
                ssP[rbase + rg * 16 + gq + 8][wc] = ssh[rg];
            }
        }
        __syncthreads();

        // each thread scatters 2 rows (one per rowgroup), parity-selected
        #pragma unroll
        for (int rg = 0; rg < 2; ++rg) {
            const int row = rbase + rg * 16 + (odd ? gq + 8 : gq);
            const float4 sp  = *(const float4*)&sP [row][0];
            const float4 ssp = *(const float4*)&ssP[row][0];
            const float st  = sp.x + sp.y + sp.z + sp.w;
            const float sst = ssp.x + ssp.y + ssp.z + ssp.w;
            const float mu   = st * (1.f / EMB);
            const float rstd = rsqrtf(sst * (1.f / EMB) - mu * mu + 1e-5f);
            const int seg = segs[row];
            float* bse = agg + (size_t)(seg < 0 ? 0 : seg) * EMB;

            #pragma unroll
            for (int nt = 0; nt < 4; ++nt) {
                const float l0 = acc[rg][nt][0], l1 = acc[rg][nt][1];
                const float h0 = acc[rg][nt][2], h1 = acc[rg][nt][3];
                const float p0 = __shfl_xor_sync(0xffffffffu, odd ? l0 : h0, 1);
                const float p1 = __shfl_xor_sync(0xffffffffu, odd ? l1 : h1, 1);
                float v0, v1, v2, v3;
                if (!odd) { v0 = l0; v1 = l1; v2 = p0; v3 = p1; }
                else      { v0 = p0; v1 = p1; v2 = h0; v3 = h1; }
                const int col4 = cbase + nt * 8 + (tig >> 1) * 4;
                const float4 gg  = *(const float4*)(g2 + col4);
                const float4 b2v = *(const float4*)(b2 + col4);
                v0 = (v0 - mu) * rstd * gg.x + b2v.x;
                v1 = (v1 - mu) * rstd * gg.y + b2v.y;
                v2 = (v2 - mu) * rstd * gg.z + b2v.z;
                v3 = (v3 - mu) * rstd * gg.w + b2v.w;
                if (seg >= 0) red_v4(bse + col4, v0, v1, v2, v3);
            }
        }
    }
}

// =====================================================================
// merge (tf32, persistent)
// =====================================================================
__global__ __launch_bounds__(256, 1)
void merge_tf32(const float* __restrict__ h, const float* __restrict__ agg,
                const float* __restrict__ Wm, const float* __restrict__ bm,
                const float* __restrict__ gm, const float* __restrict__ bmln,
                float* __restrict__ dst, int N)
{
    extern __shared__ uint32_t smu[];
    uint32_t* Wp = smu;
    uint32_t* Xs = smu + 128 * WP_STRIDE;
    float*    Xf = (float*)Xs;
    __shared__ float sP[64][2], ssP[64][2];

    const int tid  = threadIdx.x;
    const int lane = tid & 31;
    const int warp = tid >> 5;
    const int gq   = lane >> 2;
    const int tig  = lane & 3;
    const int r0   = (warp >> 1) * 16;
    const int ch   = warp & 1;
    const int pr_r = lane >> 2;
    const int pr_l = lane & 3;

    stage_W_tf32<256>(Wm, Wp, tid, 256);

    const int nTiles = (N + 63) >> 6;
    for (int tile = blockIdx.x; tile < nTiles; tile += gridDim.x) {
        const int row0 = tile * 64;
        __syncthreads();

        #pragma unroll
        for (int r = 0; r < 8; ++r) {
            const int lr  = warp * 8 + r;
            const int row = row0 + lr;
            float4 hv = make_float4(0.f, 0.f, 0.f, 0.f);
            float4 av = make_float4(0.f, 0.f, 0.f, 0.f);
            if (row < N) {
                hv = ((const float4*)(h + (size_t)row * EMB))[lane];
                av = __ldcs(((const float4*)(agg + (size_t)row * EMB)) + lane);
            }
            uint4 qh, qa;
            qh.x = f2tf(hv.x); qh.y = f2tf(hv.y); qh.z = f2tf(hv.z); qh.w = f2tf(hv.w);
            qa.x = f2tf(av.x); qa.y = f2tf(av.y); qa.z = f2tf(av.z); qa.w = f2tf(av.w);
            *(uint4*)(Xs + lr * XS2_STRIDE + lane * 4)       = qh;
            *(uint4*)(Xs + lr * XS2_STRIDE + EMB + lane * 4) = qa;
        }
        __syncthreads();

        // prefetch next tile's h/agg rows into L2
        {
            const int rown = (tile + gridDim.x) * 64 + warp * 8 + pr_r;
            if (tile + gridDim.x < nTiles && rown < N) {
                pf_l2(h   + (size_t)rown * EMB + pr_l * 32);
                pf_l2(agg + (size_t)rown * EMB + pr_l * 32);
            }
        }

        float acc[8][4];
        #pragma unroll
        for (int i = 0; i < 8; ++i)
            #pragma unroll
            for (int j = 0; j < 4; ++j) acc[i][j] = 0.f;

        mma_mainloop_half<32, XS2_STRIDE>(Xs, Wp, r0, gq, tig, ch, acc);

        float s_lo = 0.f, ss_lo = 0.f, s_hi = 0.f, ss_hi = 0.f;
        #pragma unroll
        for (int nt = 0; nt < 8; ++nt) {
            const int col = ch * 64 + nt * 8 + 2 * tig;
            const float2 bmv = *(const float2*)(bm + col);
            acc[nt][0] = fmaxf(acc[nt][0] + bmv.x, 0.f);
            acc[nt][1] = fmaxf(acc[nt][1] + bmv.y, 0.f);
            acc[nt][2] = fmaxf(acc[nt][2] + bmv.x, 0.f);
            acc[nt][3] = fmaxf(acc[nt][3] + bmv.y, 0.f);
            s_lo  += acc[nt][0] + acc[nt][1];
            ss_lo += acc[nt][0] * acc[nt][0] + acc[nt][1] * acc[nt][1];
            s_hi  += acc[nt][2] + acc[nt][3];
            ss_hi += acc[nt][2] * acc[nt][2] + acc[nt][3] * acc[nt][3];
        }
        #pragma unroll
        for (int o = 1; o < 4; o <<= 1) {
            s_lo  += __shfl_xor_sync(0xffffffffu, s_lo,  o);
            ss_lo += __shfl_xor_sync(0xffffffffu, ss_lo, o);
            s_hi  += __shfl_xor_sync(0xffffffffu, s_hi,  o);
            ss_hi += __shfl_xor_sync(0xffffffffu, ss_hi, o);
        }
        if (tig == 0) {
            sP [r0 + gq][ch]     = s_lo;  ssP[r0 + gq][ch]     = ss_lo;
            sP [r0 + gq + 8][ch] = s_hi;  ssP[r0 + gq + 8][ch] = ss_hi;
        }
        __syncthreads();

        const float st_lo  = sP [r0 + gq][0]     + sP [r0 + gq][1];
        const float sst_lo = ssP[r0 + gq][0]     + ssP[r0 + gq][1];
        const float st_hi  = sP [r0 + gq + 8][0] + sP [r0 + gq + 8][1];
        const float sst_hi = ssP[r0 + gq + 8][0] + ssP[r0 + gq + 8][1];
        const float mu_lo   = st_lo * (1.f / EMB);
        const float rstd_lo = rsqrtf(sst_lo * (1.f / EMB) - mu_lo * mu_lo + 1e-5f);
        const float mu_hi   = st_hi * (1.f / EMB);
        const float rstd_hi = rsqrtf(sst_hi * (1.f / EMB) - mu_hi * mu_hi + 1e-5f);

        #pragma unroll
        for (int nt = 0; nt < 8; ++nt) {
            const int col = ch * 64 + nt * 8 + 2 * tig;
            const float2 gg = *(const float2*)(gm + col);
            const float2 bb = *(const float2*)(bmln + col);
            float* rl = Xf + (r0 + gq)     * XS2_STRIDE + EMB + col;
            float* rh = Xf + (r0 + gq + 8) * XS2_STRIDE + EMB + col;
            rl[0] = (acc[nt][0] - mu_lo) * rstd_lo * gg.x + bb.x;
            rl[1] = (acc[nt][1] - mu_lo) * rstd_lo * gg.y + bb.y;
            rh[0] = (acc[nt][2] - mu_hi) * rstd_hi * gg.x + bb.x;
            rh[1] = (acc[nt][3] - mu_hi) * rstd_hi * gg.y + bb.y;
        }
        __syncthreads();

        #pragma unroll
        for (int r = 0; r < 8; ++r) {
            const int lr  = warp * 8 + r;
            const int row = row0 + lr;
            if (row < N) {
                const float4 hv = ((const float4*)(h + (size_t)row * EMB))[lane];
                const float4 ov = ((const float4*)(Xf + lr * XS2_STRIDE + EMB))[lane];
                float4 o;
                o.x = hv.x + ov.x; o.y = hv.y + ov.y;
                o.z = hv.z + ov.z; o.w = hv.w + ov.w;
                ((float4*)(dst + (size_t)row * EMB))[lane] = o;
            }
        }
    }
}

// =====================================================================
// host
// =====================================================================
extern "C" void kernel_launch(void* const* d_in, const int* in_sizes, int n_in,
                              void* d_out, int out_size)
{
    const float* variable_emb   = (const float*)d_in[0];
    const float* edge_emb       = (const float*)d_in[1];
    const float* constraint_emb = (const float*)d_in[2];
    const int*   e_u            = (const int*)  d_in[3];
    const int*   e_v            = (const int*)  d_in[4];
    const float* W_left   = (const float*)d_in[5];
    const float* b_left   = (const float*)d_in[6];
    const float* W_edge   = (const float*)d_in[7];
    const float* W_right  = (const float*)d_in[8];
    const float* W_join   = (const float*)d_in[9];
    const float* b_join   = (const float*)d_in[10];
    const float* W_merge  = (const float*)d_in[11];
    const float* b_merge  = (const float*)d_in[12];
    const float* g_var    = (const float*)d_in[13];
    const float* b_var    = (const float*)d_in[14];
    const float* g_edge   = (const float*)d_in[15];
    const float* b_edge   = (const float*)d_in[16];
    const float* g_con    = (const float*)d_in[17];
    const float* b_con    = (const float*)d_in[18];
    const float* g_join_ln  = (const float*)d_in[19];
    const float* b_join_ln  = (const float*)d_in[20];
    const float* g_joint    = (const float*)d_in[21];
    const float* b_joint    = (const float*)d_in[22];
    const float* g_merge    = (const float*)d_in[23];
    const float* b_merge_ln = (const float*)d_in[24];

    float* out_var = (float*)d_out;
    float* out_con = (float*)d_out + (size_t)NUv * EMB;

    float *vt, *et, *ct, *agg;
    cudaGetSymbolAddress((void**)&vt,  g_vt);
    cudaGetSymbolAddress((void**)&et,  g_et);
    cudaGetSymbolAddress((void**)&ct,  g_ct);
    cudaGetSymbolAddress((void**)&agg, g_agg);

    const int SM_MMA   = (64 * WP_STRIDE + 64 * XS_STRIDE) * 4;
    const int SM_MERGE = (128 * WP_STRIDE + 64 * XS2_STRIDE) * 4;

    cudaFuncSetAttribute(ln_gemm_tf32,   cudaFuncAttributeMaxDynamicSharedMemorySize, SM_MMA);
    cudaFuncSetAttribute(edge_join_tf32, cudaFuncAttributeMaxDynamicSharedMemorySize, SM_MMA);
    cudaFuncSetAttribute(merge_tf32,     cudaFuncAttributeMaxDynamicSharedMemorySize, SM_MERGE);

    const dim3 blk(256);

    // shared pre-transforms (vt and et identical in both passes)
    ln_gemm_tf32<<<GRID_MMA, blk, SM_MMA>>>(variable_emb, W_left, b_left, g_var, b_var, vt, NUv, 0);
    ln_gemm_tf32<<<GRID_MMA, blk, SM_MMA>>>(edge_emb, W_edge, nullptr, g_edge, b_edge, et, NEv, 1);
    ln_gemm_tf32<<<GRID_MMA, blk, SM_MMA>>>(constraint_emb, W_right, nullptr, g_con, b_con, ct, NVv, 0);

    // ---------------- pass 1: var -> con ----------------
    cudaMemsetAsync(agg, 0, (size_t)NVv * EMB * sizeof(float), 0);
    edge_join_tf32<<<GRID_MMA, blk, SM_MMA>>>(vt, et, ct, e_u, e_v, W_join, b_join,
                                              g_join_ln, b_join_ln, g_joint, b_joint,
                                              agg, /*seg_by_ev=*/1, NEv);
    merge_tf32<<<GRID_MERGE, blk, SM_MERGE>>>(ct, agg, W_merge, b_merge, g_merge, b_merge_ln,
                                              out_con, NVv);

    // ---------------- pass 2: con -> var ----------------
    ln_gemm_tf32<<<GRID_MMA, blk, SM_MMA>>>(out_con, W_right, nullptr, g_con, b_con, ct, NVv, 0);
    cudaMemsetAsync(agg, 0, (size_t)NUv * EMB * sizeof(float), 0);
    edge_join_tf32<<<GRID_MMA, blk, SM_MMA>>>(vt, et, ct, e_u, e_v, W_join, b_join,
                                              g_join_ln, b_join_ln, g_joint, b_joint,
                                              agg, /*seg_by_ev=*/0, NEv);
    merge_tf32<<<GRID_MERGE, blk, SM_MERGE>>>(vt, agg, W_merge, b_merge, g_merge, b_merge_ln,
                                              out_var, NUv);
}

// round 14
// speedup vs baseline: 1.3408x; 1.3408x over previous
#include <cuda_runtime.h>
#include <cuda_bf16.h>
#include <math.h>
#include <stdint.h>

#define EMB   128
#define NUv   100000
#define NVv   50000
#define NEv   500000

#define WP_STRIDE  264  // words per (kt,tig) W pair-row (paired b0,b1) -> LDS.64 B-frags
#define XS_STRIDE  132  // words per X row (K=128) -> conflict-free A-frag LDS
#define XS2_STRIDE 260  // words per X row (K=256) for merge

#define GRID_MMA   296  // 2 blocks/SM * 148 SMs (persistent-tile)
#define GRID_MERGE 148

// ---------------- scratch (device globals: allocation-guard-safe) ----------
__device__ float g_vt[(size_t)NUv * EMB];
__device__ float g_et[(size_t)NEv * EMB];
__device__ float g_ct[(size_t)NVv * EMB];
__device__ float g_agg[(size_t)NUv * EMB];

// ---------------- tf32 helpers ----------------
__device__ __forceinline__ uint32_t f2tf(float x) {
    uint32_t r;
    asm("cvt.rna.tf32.f32 %0, %1;" : "=r"(r) : "f"(x));
    return r;
}

__device__ __forceinline__ void mma8(float& c0, float& c1, float& c2, float& c3,
                                     uint32_t a0, uint32_t a1, uint32_t a2, uint32_t a3,
                                     uint32_t b0, uint32_t b1)
{
    asm volatile(
        "mma.sync.aligned.m16n8k8.row.col.f32.tf32.tf32.f32 "
        "{%0,%1,%2,%3}, {%4,%5,%6,%7}, {%8,%9}, {%0,%1,%2,%3};"
        : "+f"(c0), "+f"(c1), "+f"(c2), "+f"(c3)
        : "r"(a0), "r"(a1), "r"(a2), "r"(a3), "r"(b0), "r"(b1));
}

__device__ __forceinline__ void red_v4(float* p, float v0, float v1, float v2, float v3)
{
    asm volatile("red.global.add.v4.f32 [%0], {%1,%2,%3,%4};"
                 :: "l"(p), "f"(v0), "f"(v1), "f"(v2), "f"(v3) : "memory");
}

// Vectorized staging of W[KD][128] ([k][n]) into paired-tf32 smem:
//   Wp[(kt*4+tig)*WP_STRIDE + 2*n + half], k = kt*8 + half*4 + tig
template<int KD>
__device__ __forceinline__ void stage_W_tf32(const float* __restrict__ W,
                                             uint32_t* __restrict__ Wp,
                                             int tid, int nthreads)
{
    #pragma unroll 2
    for (int i = tid; i < (KD / 2) * 32; i += nthreads) {
        const int pr = i >> 5;
        const int c4 = i & 31;
        const int kt = pr >> 2, tig = pr & 3;
        const int k0 = kt * 8 + tig;
        const float4 w0 = ((const float4*)(W + (size_t)k0 * EMB))[c4];
        const float4 w1 = ((const float4*)(W + (size_t)(k0 + 4) * EMB))[c4];
        uint32_t* dst = Wp + pr * WP_STRIDE + 8 * c4;
        uint4 lo, hi;
        lo.x = f2tf(w0.x); lo.y = f2tf(w1.x); lo.z = f2tf(w0.y); lo.w = f2tf(w1.y);
        hi.x = f2tf(w0.z); hi.y = f2tf(w1.z); hi.z = f2tf(w0.w); hi.w = f2tf(w1.w);
        ((uint4*)dst)[0] = lo;
        ((uint4*)dst)[1] = hi;
    }
}

// 16-row x 64-col warp mainloop (ln_gemm / merge)
template<int NKT, int XSTR>
__device__ __forceinline__ void mma_mainloop_half(const uint32_t* __restrict__ Xs,
                                                  const uint32_t* __restrict__ Wp,
                                                  int r0, int gq, int tig, int ch,
                                                  float acc[8][4])
{
    #pragma unroll
    for (int kt = 0; kt < NKT; ++kt) {
        const uint32_t* xl = Xs + (r0 + gq) * XSTR + kt * 8;
        const uint32_t* xh = Xs + (r0 + gq + 8) * XSTR + kt * 8;
        const uint32_t a0 = xl[tig];
        const uint32_t a1 = xh[tig];
        const uint32_t a2 = xl[tig + 4];
        const uint32_t a3 = xh[tig + 4];
        const uint32_t* wrow = Wp + (kt * 4 + tig) * WP_STRIDE + 2 * (ch * 64);
        uint2 bfr[8];
        #pragma unroll
        for (int nt = 0; nt < 8; ++nt)
            bfr[nt] = *(const uint2*)(wrow + 2 * (nt * 8 + gq));
        #pragma unroll
        for (int nt = 0; nt < 8; ++nt)
            mma8(acc[nt][0], acc[nt][1], acc[nt][2], acc[nt][3],
                 a0, a1, a2, a3, bfr[nt].x, bfr[nt].y);
    }
}

// =====================================================================
// Kernel 1 (tf32, persistent): Y[row] = LN(X[row]; g,b) @ W (+bias)
// =====================================================================
__global__ __launch_bounds__(256, 2)
void ln_gemm_tf32(const float* __restrict__ X, const float* __restrict__ W,
                  const float* __restrict__ bias,
                  const float* __restrict__ g, const float* __restrict__ b,
                  float* __restrict__ Y, int N, int stream_out)
{
    extern __shared__ uint32_t smu[];
    uint32_t* Wp = smu;
    uint32_t* Xs = smu + 64 * WP_STRIDE;
    float*    Xf = (float*)Xs;

    const int tid  = threadIdx.x;
    const int lane = tid & 31;
    const int warp = tid >> 5;
    const int gq   = lane >> 2;
    const int tig  = lane & 3;
    const int r0   = (warp >> 1) * 16;
    const int ch   = warp & 1;

    stage_W_tf32<128>(W, Wp, tid, 256);

    const float4 gv = ((const float4*)g)[lane];
    const float4 bv = ((const float4*)b)[lane];
    float4 bb = make_float4(0.f, 0.f, 0.f, 0.f);
    if (bias) bb = ((const float4*)bias)[lane];

    const int nTiles = (N + 63) >> 6;
    for (int tile = blockIdx.x; tile < nTiles; tile += gridDim.x) {
        const int row0 = tile * 64;
        __syncthreads();

        #pragma unroll
        for (int r = 0; r < 8; ++r) {
            const int lr  = warp * 8 + r;
            const int row = row0 + lr;
            float4 xv = make_float4(0.f, 0.f, 0.f, 0.f);
            if (row < N) xv = __ldcs(((const float4*)(X + (size_t)row * EMB)) + lane);
            float s  = xv.x + xv.y + xv.z + xv.w;
            float ss = xv.x * xv.x + xv.y * xv.y + xv.z * xv.z + xv.w * xv.w;
            #pragma unroll
            for (int o = 16; o; o >>= 1) {
                s  += __shfl_xor_sync(0xffffffffu, s,  o);
                ss += __shfl_xor_sync(0xffffffffu, ss, o);
            }
            const float mu   = s * (1.f / EMB);
            const float rstd = rsqrtf(ss * (1.f / EMB) - mu * mu + 1e-5f);
            uint4 q;
            q.x = f2tf((xv.x - mu) * rstd * gv.x + bv.x);
            q.y = f2tf((xv.y - mu) * rstd * gv.y + bv.y);
            q.z = f2tf((xv.z - mu) * rstd * gv.z + bv.z);
            q.w = f2tf((xv.w - mu) * rstd * gv.w + bv.w);
            *(uint4*)(Xs + lr * XS_STRIDE + lane * 4) = q;
        }
        __syncthreads();

        float acc[8][4];
        #pragma unroll
        for (int i = 0; i < 8; ++i)
            #pragma unroll
            for (int j = 0; j < 4; ++j) acc[i][j] = 0.f;

        mma_mainloop_half<16, XS_STRIDE>(Xs, Wp, r0, gq, tig, ch, acc);

        __syncthreads();
        #pragma unroll
        for (int nt = 0; nt < 8; ++nt) {
            const int col = ch * 64 + nt * 8 + 2 * tig;
            float* rl = Xf + (r0 + gq)     * XS_STRIDE + col;
            float* rh = Xf + (r0 + gq + 8) * XS_STRIDE + col;
            rl[0] = acc[nt][0]; rl[1] = acc[nt][1];
            rh[0] = acc[nt][2]; rh[1] = acc[nt][3];
        }
        __syncthreads();

        #pragma unroll
        for (int r = 0; r < 8; ++r) {
            const int lr  = warp * 8 + r;
            const int row = row0 + lr;
            if (row < N) {
                float4 o = ((const float4*)(Xf + lr * XS_STRIDE))[lane];
                o.x += bb.x; o.y += bb.y; o.z += bb.z; o.w += bb.w;
                if (stream_out) __stcs(((float4*)(Y + (size_t)row * EMB)) + lane, o);
                else            ((float4*)(Y + (size_t)row * EMB))[lane] = o;
            }
        }
    }
}

// =====================================================================
// Kernel 2 (tf32, persistent): fused edge join + LN + GEMM + LN + red.v4
// Warp tiling 32x32; epilogue params (bj/g2/b2) cached in smem.
// =====================================================================
__global__ __launch_bounds__(256, 2)
void edge_join_tf32(const float* __restrict__ vt, const float* __restrict__ et,
                    const float* __restrict__ ct,
                    const int* __restrict__ e_u, const int* __restrict__ e_v,
                    const float* __restrict__ Wj, const float* __restrict__ bj,
                    const float* __restrict__ g1, const float* __restrict__ b1,
                    const float* __restrict__ g2, const float* __restrict__ b2,
                    float* __restrict__ agg, int seg_by_ev, int NE)
{
    extern __shared__ uint32_t smu[];
    uint32_t* Wp  = smu;
    uint32_t* Xs  = smu + 64 * WP_STRIDE;
    float*    prm = (float*)(smu + 64 * WP_STRIDE + 64 * XS_STRIDE); // bj|g2|b2
    __shared__ int   segs[64];
    __shared__ float sP[64][4], ssP[64][4];

    const int tid  = threadIdx.x;
    const int lane = tid & 31;
    const int warp = tid >> 5;
    const int gq   = lane >> 2;
    const int tig  = lane & 3;
    const int wr   = warp >> 2;        // 0-1: row half (32 rows)
    const int wc   = warp & 3;         // 0-3: col quarter (32 cols)
    const int rbase = wr * 32;
    const int cbase = wc * 32;
    const bool odd  = (tig & 1);

    stage_W_tf32<128>(Wj, Wp, tid, 256);
    if (tid < 128) {
        prm[tid]       = bj[tid];
        prm[128 + tid] = g2[tid];
        prm[256 + tid] = b2[tid];
    }

    const float4 g1v = ((const float4*)g1)[lane];
    const float4 b1v = ((const float4*)b1)[lane];

    const int nTiles = (NE + 63) >> 6;
    for (int tile = blockIdx.x; tile < nTiles; tile += gridDim.x) {
        const int e0 = tile * 64;
        __syncthreads();

        // ---- stage: warp stages rows warp*8..+8 ----
        int iu[8], iv[8];
        #pragma unroll
        for (int r = 0; r < 8; ++r) {
            const int e = e0 + warp * 8 + r;
            iu[r] = (e < NE) ? __ldg(e_u + e) : -1;
            iv[r] = (e < NE) ? __ldg(e_v + e) : -1;
        }
        if (lane == 0) {
            #pragma unroll
            for (int r = 0; r < 8; ++r)
                segs[warp * 8 + r] = (iu[r] < 0) ? -1 : (seg_by_ev ? iv[r] : iu[r]);
        }

        #pragma unroll
        for (int r = 0; r < 8; ++r) {
            const int lr = warp * 8 + r;
            const int e  = e0 + lr;
            float4 xv = make_float4(0.f, 0.f, 0.f, 0.f);
            if (iu[r] >= 0) {
                const float4 m = __ldcs(((const float4*)(et + (size_t)e * EMB)) + lane);
                const float4 a = ((const float4*)(vt + (size_t)iu[r] * EMB))[lane];
                const float4 c = ((const float4*)(ct + (size_t)iv[r] * EMB))[lane];
                xv.x = fmaxf(a.x + m.x + c.x, 0.f);
                xv.y = fmaxf(a.y + m.y + c.y, 0.f);
                xv.z = fmaxf(a.z + m.z + c.z, 0.f);
                xv.w = fmaxf(a.w + m.w + c.w, 0.f);
            }
            float s  = xv.x + xv.y + xv.z + xv.w;
            float ss = xv.x * xv.x + xv.y * xv.y + xv.z * xv.z + xv.w * xv.w;
            #pragma unroll
            for (int o = 16; o; o >>= 1) {
                s  += __shfl_xor_sync(0xffffffffu, s,  o);
                ss += __shfl_xor_sync(0xffffffffu, ss, o);
            }
            const float mu   = s * (1.f / EMB);
            const float rstd = rsqrtf(ss * (1.f / EMB) - mu * mu + 1e-5f);
            uint4 q;
            q.x = f2tf((xv.x - mu) * rstd * g1v.x + b1v.x);
            q.y = f2tf((xv.y - mu) * rstd * g1v.y + b1v.y);
            q.z = f2tf((xv.z - mu) * rstd * g1v.z + b1v.z);
            q.w = f2tf((xv.w - mu) * rstd * g1v.w + b1v.w);
            *(uint4*)(Xs + lr * XS_STRIDE + lane * 4) = q;
        }
        __syncthreads();

        // ---- mainloop: 2 rowgroups x 4 nt, B-frags shared across rowgroups
        float acc[2][4][4];
        #pragma unroll
        for (int rg = 0; rg < 2; ++rg)
            #pragma unroll
            for (int nt = 0; nt < 4; ++nt)
                #pragma unroll
                for (int j = 0; j < 4; ++j) acc[rg][nt][j] = 0.f;

        #pragma unroll
        for (int kt = 0; kt < 16; ++kt) {
            uint32_t a[2][4];
            #pragma unroll
            for (int rg = 0; rg < 2; ++rg) {
                const uint32_t* xl = Xs + (rbase + rg * 16 + gq) * XS_STRIDE + kt * 8;
                const uint32_t* xh = Xs + (rbase + rg * 16 + gq + 8) * XS_STRIDE + kt * 8;
                a[rg][0] = xl[tig];
                a[rg][1] = xh[tig];
                a[rg][2] = xl[tig + 4];
                a[rg][3] = xh[tig + 4];
            }
            const uint32_t* wrow = Wp + (kt * 4 + tig) * WP_STRIDE + 2 * cbase;
            uint2 bfr[4];
            #pragma unroll
            for (int nt = 0; nt < 4; ++nt)
                bfr[nt] = *(const uint2*)(wrow + 2 * (nt * 8 + gq));
            #pragma unroll
            for (int rg = 0; rg < 2; ++rg)
                #pragma unroll
                for (int nt = 0; nt < 4; ++nt)
                    mma8(acc[rg][nt][0], acc[rg][nt][1], acc[rg][nt][2], acc[rg][nt][3],
                         a[rg][0], a[rg][1], a[rg][2], a[rg][3], bfr[nt].x, bfr[nt].y);
        }

        // ---- epilogue: +bias, per-row partial stats (32-col partials) ----
        float sl[2] = {0.f, 0.f}, ssl[2] = {0.f, 0.f};
        float sh[2] = {0.f, 0.f}, ssh[2] = {0.f, 0.f};
        #pragma unroll
        for (int rg = 0; rg < 2; ++rg)
            #pragma unroll
            for (int nt = 0; nt < 4; ++nt) {
                const int col = cbase + nt * 8 + 2 * tig;
                const float2 bjv = *(const float2*)(prm + col);
                acc[rg][nt][0] += bjv.x; acc[rg][nt][1] += bjv.y;
                acc[rg][nt][2] += bjv.x; acc[rg][nt][3] += bjv.y;
                sl[rg]  += acc[rg][nt][0] + acc[rg][nt][1];
                ssl[rg] += acc[rg][nt][0] * acc[rg][nt][0] + acc[rg][nt][1] * acc[rg][nt][1];
                sh[rg]  += acc[rg][nt][2] + acc[rg][nt][3];
                ssh[rg] += acc[rg][nt][2] * acc[rg][nt][2] + acc[rg][nt][3] * acc[rg][nt][3];
            }
        #pragma unroll
        for (int o = 1; o < 4; o <<= 1) {
            #pragma unroll
            for (int rg = 0; rg < 2; ++rg) {
                sl[rg]  += __shfl_xor_sync(0xffffffffu, sl[rg],  o);
                ssl[rg] += __shfl_xor_sync(0xffffffffu, ssl[rg], o);
                sh[rg]  += __shfl_xor_sync(0xffffffffu, sh[rg],  o);
                ssh[rg] += __shfl_xor_sync(0xffffffffu, ssh[rg], o);
            }
        }
        if (tig == 0) {
            #pragma unroll
            for (int rg = 0; rg < 2; ++rg) {
                sP [rbase + rg * 16 + gq][wc]     = sl[rg];
                ssP[rbase + rg * 16 + gq][wc]     = ssl[rg];
                sP [rbase + rg * 16 + gq + 8][wc] = sh[rg];
                ssP[rbase + rg * 16 + gq + 8][wc] = ssh[rg];
            }
        }
        __syncthreads();

        // each thread scatters 2 rows (one per rowgroup), parity-selected
        #pragma unroll
        for (int rg = 0; rg < 2; ++rg) {
            const int row = rbase + rg * 16 + (odd ? gq + 8 : gq);
            const float4 sp  = *(const float4*)&sP [row][0];
            const float4 ssp = *(const float4*)&ssP[row][0];
            const float st  = sp.x + sp.y + sp.z + sp.w;
            const float sst = ssp.x + ssp.y + ssp.z + ssp.w;
            const float mu   = st * (1.f / EMB);
            const float rstd = rsqrtf(sst * (1.f / EMB) - mu * mu + 1e-5f);
            const int seg = segs[row];
            float* bse = agg + (size_t)(seg < 0 ? 0 : seg) * EMB;

            #pragma unroll
            for (int nt = 0; nt < 4; ++nt) {
                const float l0 = acc[rg][nt][0], l1 = acc[rg][nt][1];
                const float h0 = acc[rg][nt][2], h1 = acc[rg][nt][3];
                const float p0 = __shfl_xor_sync(0xffffffffu, odd ? l0 : h0, 1);
                const float p1 = __shfl_xor_sync(0xffffffffu, odd ? l1 : h1, 1);
                float v0, v1, v2, v3;
                if (!odd) { v0 = l0; v1 = l1; v2 = p0; v3 = p1; }
                else      { v0 = p0; v1 = p1; v2 = h0; v3 = h1; }
                const int col4 = cbase + nt * 8 + (tig >> 1) * 4;
                const float4 gg  = *(const float4*)(prm + 128 + col4);
                const float4 b2v = *(const float4*)(prm + 256 + col4);
                v0 = (v0 - mu) * rstd * gg.x + b2v.x;
                v1 = (v1 - mu) * rstd * gg.y + b2v.y;
                v2 = (v2 - mu) * rstd * gg.z + b2v.z;
                v3 = (v3 - mu) * rstd * gg.w + b2v.w;
                if (seg >= 0) red_v4(bse + col4, v0, v1, v2, v3);
            }
        }
    }
}

// =====================================================================
// merge (tf32, persistent)
// =====================================================================
__global__ __launch_bounds__(256, 1)
void merge_tf32(const float* __restrict__ h, const float* __restrict__ agg,
                const float* __restrict__ Wm, const float* __restrict__ bm,
                const float* __restrict__ gm, const float* __restrict__ bmln,
                float* __restrict__ dst, int N)
{
    extern __shared__ uint32_t smu[];
    uint32_t* Wp = smu;
    uint32_t* Xs = smu + 128 * WP_STRIDE;
    float*    Xf = (float*)Xs;
    __shared__ float sP[64][2], ssP[64][2];

    const int tid  = threadIdx.x;
    const int lane = tid & 31;
    const int warp = tid >> 5;
    const int gq   = lane >> 2;
    const int tig  = lane & 3;
    const int r0   = (warp >> 1) * 16;
    const int ch   = warp & 1;

    stage_W_tf32<256>(Wm, Wp, tid, 256);

    const int nTiles = (N + 63) >> 6;
    for (int tile = blockIdx.x; tile < nTiles; tile += gridDim.x) {
        const int row0 = tile * 64;
        __syncthreads();

        #pragma unroll
        for (int r = 0; r < 8; ++r) {
            const int lr  = warp * 8 + r;
            const int row = row0 + lr;
            float4 hv = make_float4(0.f, 0.f, 0.f, 0.f);
            float4 av = make_float4(0.f, 0.f, 0.f, 0.f);
            if (row < N) {
                hv = ((const float4*)(h + (size_t)row * EMB))[lane];
                av = __ldcs(((const float4*)(agg + (size_t)row * EMB)) + lane);
            }
            uint4 qh, qa;
            qh.x = f2tf(hv.x); qh.y = f2tf(hv.y); qh.z = f2tf(hv.z); qh.w = f2tf(hv.w);
            qa.x = f2tf(av.x); qa.y = f2tf(av.y); qa.z = f2tf(av.z); qa.w = f2tf(av.w);
            *(uint4*)(Xs + lr * XS2_STRIDE + lane * 4)       = qh;
            *(uint4*)(Xs + lr * XS2_STRIDE + EMB + lane * 4) = qa;
        }
        __syncthreads();

        float acc[8][4];
        #pragma unroll
        for (int i = 0; i < 8; ++i)
            #pragma unroll
            for (int j = 0; j < 4; ++j) acc[i][j] = 0.f;

        mma_mainloop_half<32, XS2_STRIDE>(Xs, Wp, r0, gq, tig, ch, acc);

        float s_lo = 0.f, ss_lo = 0.f, s_hi = 0.f, ss_hi = 0.f;
        #pragma unroll
        for (int nt = 0; nt < 8; ++nt) {
            const int col = ch * 64 + nt * 8 + 2 * tig;
            const float2 bmv = *(const float2*)(bm + col);
            acc[nt][0] = fmaxf(acc[nt][0] + bmv.x, 0.f);
            acc[nt][1] = fmaxf(acc[nt][1] + bmv.y, 0.f);
            acc[nt][2] = fmaxf(acc[nt][2] + bmv.x, 0.f);
            acc[nt][3] = fmaxf(acc[nt][3] + bmv.y, 0.f);
            s_lo  += acc[nt][0] + acc[nt][1];
            ss_lo += acc[nt][0] * acc[nt][0] + acc[nt][1] * acc[nt][1];
            s_hi  += acc[nt][2] + acc[nt][3];
            ss_hi += acc[nt][2] * acc[nt][2] + acc[nt][3] * acc[nt][3];
        }
        #pragma unroll
        for (int o = 1; o < 4; o <<= 1) {
            s_lo  += __shfl_xor_sync(0xffffffffu, s_lo,  o);
            ss_lo += __shfl_xor_sync(0xffffffffu, ss_lo, o);
            s_hi  += __shfl_xor_sync(0xffffffffu, s_hi,  o);
            ss_hi += __shfl_xor_sync(0xffffffffu, ss_hi, o);
        }
        if (tig == 0) {
            sP [r0 + gq][ch]     = s_lo;  ssP[r0 + gq][ch]     = ss_lo;
            sP [r0 + gq + 8][ch] = s_hi;  ssP[r0 + gq + 8][ch] = ss_hi;
        }
        __syncthreads();

        const float st_lo  = sP [r0 + gq][0]     + sP [r0 + gq][1];
        const float sst_lo = ssP[r0 + gq][0]     + ssP[r0 + gq][1];
        const float st_hi  = sP [r0 + gq + 8][0] + sP [r0 + gq + 8][1];
        const float sst_hi = ssP[r0 + gq + 8][0] + ssP[r0 + gq + 8][1];
        const float mu_lo   = st_lo * (1.f / EMB);
        const float rstd_lo = rsqrtf(sst_lo * (1.f / EMB) - mu_lo * mu_lo + 1e-5f);
        const float mu_hi   = st_hi * (1.f / EMB);
        const float rstd_hi = rsqrtf(sst_hi * (1.f / EMB) - mu_hi * mu_hi + 1e-5f);

        #pragma unroll
        for (int nt = 0; nt < 8; ++nt) {
            const int col = ch * 64 + nt * 8 + 2 * tig;
            const float2 gg = *(const float2*)(gm + col);
            const float2 bb = *(const float2*)(bmln + col);
            float* rl = Xf + (r0 + gq)     * XS2_STRIDE + EMB + col;
            float* rh = Xf + (r0 + gq + 8) * XS2_STRIDE + EMB + col;
            rl[0] = (acc[nt][0] - mu_lo) * rstd_lo * gg.x + bb.x;
            rl[1] = (acc[nt][1] - mu_lo) * rstd_lo * gg.y + bb.y;
            rh[0] = (acc[nt][2] - mu_hi) * rstd_hi * gg.x + bb.x;
            rh[1] = (acc[nt][3] - mu_hi) * rstd_hi * gg.y + bb.y;
        }
        __syncthreads();

        #pragma unroll
        for (int r = 0; r < 8; ++r) {
            const int lr  = warp * 8 + r;
            const int row = row0 + lr;
            if (row < N) {
                const float4 hv = ((const float4*)(h + (size_t)row * EMB))[lane];
                const float4 ov = ((const float4*)(Xf + lr * XS2_STRIDE + EMB))[lane];
                float4 o;
                o.x = hv.x + ov.x; o.y = hv.y + ov.y;
                o.z = hv.z + ov.z; o.w = hv.w + ov.w;
                ((float4*)(dst + (size_t)row * EMB))[lane] = o;
            }
        }
    }
}

// =====================================================================
// host
// =====================================================================
extern "C" void kernel_launch(void* const* d_in, const int* in_sizes, int n_in,
                              void* d_out, int out_size)
{
    const float* variable_emb   = (const float*)d_in[0];
    const float* edge_emb       = (const float*)d_in[1];
    const float* constraint_emb = (const float*)d_in[2];
    const int*   e_u            = (const int*)  d_in[3];
    const int*   e_v            = (const int*)  d_in[4];
    const float* W_left   = (const float*)d_in[5];
    const float* b_left   = (const float*)d_in[6];
    const float* W_edge   = (const float*)d_in[7];
    const float* W_right  = (const float*)d_in[8];
    const float* W_join   = (const float*)d_in[9];
    const float* b_join   = (const float*)d_in[10];
    const float* W_merge  = (const float*)d_in[11];
    const float* b_merge  = (const float*)d_in[12];
    const float* g_var    = (const float*)d_in[13];
    const float* b_var    = (const float*)d_in[14];
    const float* g_edge   = (const float*)d_in[15];
    const float* b_edge   = (const float*)d_in[16];
    const float* g_con    = (const float*)d_in[17];
    const float* b_con    = (const float*)d_in[18];
    const float* g_join_ln  = (const float*)d_in[19];
    const float* b_join_ln  = (const float*)d_in[20];
    const float* g_joint    = (const float*)d_in[21];
    const float* b_joint    = (const float*)d_in[22];
    const float* g_merge    = (const float*)d_in[23];
    const float* b_merge_ln = (const float*)d_in[24];

    float* out_var = (float*)d_out;
    float* out_con = (float*)d_out + (size_t)NUv * EMB;

    float *vt, *et, *ct, *agg;
    cudaGetSymbolAddress((void**)&vt,  g_vt);
    cudaGetSymbolAddress((void**)&et,  g_et);
    cudaGetSymbolAddress((void**)&ct,  g_ct);
    cudaGetSymbolAddress((void**)&agg, g_agg);

    const int SM_MMA   = (64 * WP_STRIDE + 64 * XS_STRIDE) * 4;
    const int SM_EJ    = (64 * WP_STRIDE + 64 * XS_STRIDE + 384) * 4;   // + bj|g2|b2
    const int SM_MERGE = (128 * WP_STRIDE + 64 * XS2_STRIDE) * 4;

    cudaFuncSetAttribute(ln_gemm_tf32,   cudaFuncAttributeMaxDynamicSharedMemorySize, SM_MMA);
    cudaFuncSetAttribute(edge_join_tf32, cudaFuncAttributeMaxDynamicSharedMemorySize, SM_EJ);
    cudaFuncSetAttribute(merge_tf32,     cudaFuncAttributeMaxDynamicSharedMemorySize, SM_MERGE);

    const dim3 blk(256);

    // shared pre-transforms (vt and et identical in both passes)
    ln_gemm_tf32<<<GRID_MMA, blk, SM_MMA>>>(variable_emb, W_left, b_left, g_var, b_var, vt, NUv, 0);
    ln_gemm_tf32<<<GRID_MMA, blk, SM_MMA>>>(edge_emb, W_edge, nullptr, g_edge, b_edge, et, NEv, 1);
    ln_gemm_tf32<<<GRID_MMA, blk, SM_MMA>>>(constraint_emb, W_right, nullptr, g_con, b_con, ct, NVv, 0);

    // ---------------- pass 1: var -> con ----------------
    cudaMemsetAsync(agg, 0, (size_t)NVv * EMB * sizeof(float), 0);
    edge_join_tf32<<<GRID_MMA, blk, SM_EJ>>>(vt, et, ct, e_u, e_v, W_join, b_join,
                                             g_join_ln, b_join_ln, g_joint, b_joint,
                                             agg, /*seg_by_ev=*/1, NEv);
    merge_tf32<<<GRID_MERGE, blk, SM_MERGE>>>(ct, agg, W_merge, b_merge, g_merge, b_merge_ln,
                                              out_con, NVv);

    // ---------------- pass 2: con -> var ----------------
    ln_gemm_tf32<<<GRID_MMA, blk, SM_MMA>>>(out_con, W_right, nullptr, g_con, b_con, ct, NVv, 0);
    cudaMemsetAsync(agg, 0, (size_t)NUv * EMB * sizeof(float), 0);
    edge_join_tf32<<<GRID_MMA, blk, SM_EJ>>>(vt, et, ct, e_u, e_v, W_join, b_join,
                                             g_join_ln, b_join_ln, g_joint, b_joint,
                                             agg, /*seg_by_ev=*/0, NEv);
    merge_tf32<<<GRID_MERGE, blk, SM_MERGE>>>(vt, agg, W_merge, b_merge, g_merge, b_merge_ln,
                                              out_var, NUv);
}

// round 15
// speedup vs baseline: 1.3800x; 1.0292x over previous
#include <cuda_runtime.h>
#include <cuda_bf16.h>
#include <math.h>
#include <stdint.h>

#define EMB   128
#define NUv   100000
#define NVv   50000
#define NEv   500000

#define WP_STRIDE  264  // words per (kt,tig) W pair-row (paired b0,b1) -> LDS.64 B-frags
#define XS_STRIDE  132  // words per X row (K=128) -> conflict-free A-frag LDS
#define XS2_STRIDE 260  // words per X row (K=256) for merge

#define GRID_MMA   296  // 2 blocks/SM * 148 SMs (persistent-tile)
#define GRID_MERGE 148

// ---------------- scratch (device globals: allocation-guard-safe) ----------
__device__ float g_vt[(size_t)NUv * EMB];
__device__ float g_et[(size_t)NEv * EMB];
__device__ float g_ct[(size_t)NVv * EMB];
__device__ float g_agg[(size_t)NUv * EMB];

// ---------------- tf32 helpers ----------------
__device__ __forceinline__ uint32_t f2tf(float x) {
    uint32_t r;
    asm("cvt.rna.tf32.f32 %0, %1;" : "=r"(r) : "f"(x));
    return r;
}

__device__ __forceinline__ void mma8(float& c0, float& c1, float& c2, float& c3,
                                     uint32_t a0, uint32_t a1, uint32_t a2, uint32_t a3,
                                     uint32_t b0, uint32_t b1)
{
    asm volatile(
        "mma.sync.aligned.m16n8k8.row.col.f32.tf32.tf32.f32 "
        "{%0,%1,%2,%3}, {%4,%5,%6,%7}, {%8,%9}, {%0,%1,%2,%3};"
        : "+f"(c0), "+f"(c1), "+f"(c2), "+f"(c3)
        : "r"(a0), "r"(a1), "r"(a2), "r"(a3), "r"(b0), "r"(b1));
}

__device__ __forceinline__ void red_v4(float* p, float v0, float v1, float v2, float v3)
{
    asm volatile("red.global.add.v4.f32 [%0], {%1,%2,%3,%4};"
                 :: "l"(p), "f"(v0), "f"(v1), "f"(v2), "f"(v3) : "memory");
}

// Vectorized staging of W[KD][128] ([k][n]) into paired-tf32 smem:
//   Wp[(kt*4+tig)*WP_STRIDE + 2*n + half], k = kt*8 + half*4 + tig
template<int KD>
__device__ __forceinline__ void stage_W_tf32(const float* __restrict__ W,
                                             uint32_t* __restrict__ Wp,
                                             int tid, int nthreads)
{
    #pragma unroll 2
    for (int i = tid; i < (KD / 2) * 32; i += nthreads) {
        const int pr = i >> 5;
        const int c4 = i & 31;
        const int kt = pr >> 2, tig = pr & 3;
        const int k0 = kt * 8 + tig;
        const float4 w0 = ((const float4*)(W + (size_t)k0 * EMB))[c4];
        const float4 w1 = ((const float4*)(W + (size_t)(k0 + 4) * EMB))[c4];
        uint32_t* dst = Wp + pr * WP_STRIDE + 8 * c4;
        uint4 lo, hi;
        lo.x = f2tf(w0.x); lo.y = f2tf(w1.x); lo.z = f2tf(w0.y); lo.w = f2tf(w1.y);
        hi.x = f2tf(w0.z); hi.y = f2tf(w1.z); hi.z = f2tf(w0.w); hi.w = f2tf(w1.w);
        ((uint4*)dst)[0] = lo;
        ((uint4*)dst)[1] = hi;
    }
}

// 16-row x 64-col warp mainloop (ln_gemm / merge)
template<int NKT, int XSTR>
__device__ __forceinline__ void mma_mainloop_half(const uint32_t* __restrict__ Xs,
                                                  const uint32_t* __restrict__ Wp,
                                                  int r0, int gq, int tig, int ch,
                                                  float acc[8][4])
{
    #pragma unroll
    for (int kt = 0; kt < NKT; ++kt) {
        const uint32_t* xl = Xs + (r0 + gq) * XSTR + kt * 8;
        const uint32_t* xh = Xs + (r0 + gq + 8) * XSTR + kt * 8;
        const uint32_t a0 = xl[tig];
        const uint32_t a1 = xh[tig];
        const uint32_t a2 = xl[tig + 4];
        const uint32_t a3 = xh[tig + 4];
        const uint32_t* wrow = Wp + (kt * 4 + tig) * WP_STRIDE + 2 * (ch * 64);
        uint2 bfr[8];
        #pragma unroll
        for (int nt = 0; nt < 8; ++nt)
            bfr[nt] = *(const uint2*)(wrow + 2 * (nt * 8 + gq));
        #pragma unroll
        for (int nt = 0; nt < 8; ++nt)
            mma8(acc[nt][0], acc[nt][1], acc[nt][2], acc[nt][3],
                 a0, a1, a2, a3, bfr[nt].x, bfr[nt].y);
    }
}

// =====================================================================
// Kernel 1 (tf32, persistent): Y[row] = LN(X[row]; g,b) @ W (+bias)
// =====================================================================
__global__ __launch_bounds__(256, 2)
void ln_gemm_tf32(const float* __restrict__ X, const float* __restrict__ W,
                  const float* __restrict__ bias,
                  const float* __restrict__ g, const float* __restrict__ b,
                  float* __restrict__ Y, int N, int stream_out)
{
    extern __shared__ uint32_t smu[];
    uint32_t* Wp = smu;
    uint32_t* Xs = smu + 64 * WP_STRIDE;
    float*    Xf = (float*)Xs;

    const int tid  = threadIdx.x;
    const int lane = tid & 31;
    const int warp = tid >> 5;
    const int gq   = lane >> 2;
    const int tig  = lane & 3;
    const int r0   = (warp >> 1) * 16;
    const int ch   = warp & 1;

    stage_W_tf32<128>(W, Wp, tid, 256);

    const float4 gv = ((const float4*)g)[lane];
    const float4 bv = ((const float4*)b)[lane];
    float4 bb = make_float4(0.f, 0.f, 0.f, 0.f);
    if (bias) bb = ((const float4*)bias)[lane];

    const int nTiles = (N + 63) >> 6;
    for (int tile = blockIdx.x; tile < nTiles; tile += gridDim.x) {
        const int row0 = tile * 64;
        __syncthreads();

        #pragma unroll
        for (int r = 0; r < 8; ++r) {
            const int lr  = warp * 8 + r;
            const int row = row0 + lr;
            float4 xv = make_float4(0.f, 0.f, 0.f, 0.f);
            if (row < N) xv = __ldcs(((const float4*)(X + (size_t)row * EMB)) + lane);
            float s  = xv.x + xv.y + xv.z + xv.w;
            float ss = xv.x * xv.x + xv.y * xv.y + xv.z * xv.z + xv.w * xv.w;
            #pragma unroll
            for (int o = 16; o; o >>= 1) {
                s  += __shfl_xor_sync(0xffffffffu, s,  o);
                ss += __shfl_xor_sync(0xffffffffu, ss, o);
            }
            const float mu   = s * (1.f / EMB);
            const float rstd = rsqrtf(ss * (1.f / EMB) - mu * mu + 1e-5f);
            uint4 q;
            q.x = f2tf((xv.x - mu) * rstd * gv.x + bv.x);
            q.y = f2tf((xv.y - mu) * rstd * gv.y + bv.y);
            q.z = f2tf((xv.z - mu) * rstd * gv.z + bv.z);
            q.w = f2tf((xv.w - mu) * rstd * gv.w + bv.w);
            *(uint4*)(Xs + lr * XS_STRIDE + lane * 4) = q;
        }
        __syncthreads();

        float acc[8][4];
        #pragma unroll
        for (int i = 0; i < 8; ++i)
            #pragma unroll
            for (int j = 0; j < 4; ++j) acc[i][j] = 0.f;

        mma_mainloop_half<16, XS_STRIDE>(Xs, Wp, r0, gq, tig, ch, acc);

        __syncthreads();
        #pragma unroll
        for (int nt = 0; nt < 8; ++nt) {
            const int col = ch * 64 + nt * 8 + 2 * tig;
            float* rl = Xf + (r0 + gq)     * XS_STRIDE + col;
            float* rh = Xf + (r0 + gq + 8) * XS_STRIDE + col;
            rl[0] = acc[nt][0]; rl[1] = acc[nt][1];
            rh[0] = acc[nt][2]; rh[1] = acc[nt][3];
        }
        __syncthreads();

        #pragma unroll
        for (int r = 0; r < 8; ++r) {
            const int lr  = warp * 8 + r;
            const int row = row0 + lr;
            if (row < N) {
                float4 o = ((const float4*)(Xf + lr * XS_STRIDE))[lane];
                o.x += bb.x; o.y += bb.y; o.z += bb.z; o.w += bb.w;
                if (stream_out) __stcs(((float4*)(Y + (size_t)row * EMB)) + lane, o);
                else            ((float4*)(Y + (size_t)row * EMB))[lane] = o;
            }
        }
    }
}

// =====================================================================
// Kernel 2 (tf32, persistent): fused edge join + LN + GEMM + LN + red.v4
// Warp tiling: 32 rows x 32 cols (2 rowgroups x 4 nt); B-frags reused
// across rowgroups. et loads streaming. (R11 configuration.)
// =====================================================================
__global__ __launch_bounds__(256, 2)
void edge_join_tf32(const float* __restrict__ vt, const float* __restrict__ et,
                    const float* __restrict__ ct,
                    const int* __restrict__ e_u, const int* __restrict__ e_v,
                    const float* __restrict__ Wj, const float* __restrict__ bj,
                    const float* __restrict__ g1, const float* __restrict__ b1,
                    const float* __restrict__ g2, const float* __restrict__ b2,
                    float* __restrict__ agg, int seg_by_ev, int NE)
{
    extern __shared__ uint32_t smu[];
    uint32_t* Wp = smu;
    uint32_t* Xs = smu + 64 * WP_STRIDE;
    __shared__ int   segs[64];
    __shared__ float sP[64][4], ssP[64][4];

    const int tid  = threadIdx.x;
    const int lane = tid & 31;
    const int warp = tid >> 5;
    const int gq   = lane >> 2;
    const int tig  = lane & 3;
    const int wr   = warp >> 2;        // 0-1: row half (32 rows)
    const int wc   = warp & 3;         // 0-3: col quarter (32 cols)
    const int rbase = wr * 32;
    const int cbase = wc * 32;
    const bool odd  = (tig & 1);

    stage_W_tf32<128>(Wj, Wp, tid, 256);

    const float4 g1v = ((const float4*)g1)[lane];
    const float4 b1v = ((const float4*)b1)[lane];

    const int nTiles = (NE + 63) >> 6;
    for (int tile = blockIdx.x; tile < nTiles; tile += gridDim.x) {
        const int e0 = tile * 64;
        __syncthreads();

        // ---- stage: warp stages rows warp*8..+8 ----
        int iu[8], iv[8];
        #pragma unroll
        for (int r = 0; r < 8; ++r) {
            const int e = e0 + warp * 8 + r;
            iu[r] = (e < NE) ? __ldg(e_u + e) : -1;
            iv[r] = (e < NE) ? __ldg(e_v + e) : -1;
        }
        if (lane == 0) {
            #pragma unroll
            for (int r = 0; r < 8; ++r)
                segs[warp * 8 + r] = (iu[r] < 0) ? -1 : (seg_by_ev ? iv[r] : iu[r]);
        }

        #pragma unroll
        for (int r = 0; r < 8; ++r) {
            const int lr = warp * 8 + r;
            const int e  = e0 + lr;
            float4 xv = make_float4(0.f, 0.f, 0.f, 0.f);
            if (iu[r] >= 0) {
                const float4 m = __ldcs(((const float4*)(et + (size_t)e * EMB)) + lane);
                const float4 a = ((const float4*)(vt + (size_t)iu[r] * EMB))[lane];
                const float4 c = ((const float4*)(ct + (size_t)iv[r] * EMB))[lane];
                xv.x = fmaxf(a.x + m.x + c.x, 0.f);
                xv.y = fmaxf(a.y + m.y + c.y, 0.f);
                xv.z = fmaxf(a.z + m.z + c.z, 0.f);
                xv.w = fmaxf(a.w + m.w + c.w, 0.f);
            }
            float s  = xv.x + xv.y + xv.z + xv.w;
            float ss = xv.x * xv.x + xv.y * xv.y + xv.z * xv.z + xv.w * xv.w;
            #pragma unroll
            for (int o = 16; o; o >>= 1) {
                s  += __shfl_xor_sync(0xffffffffu, s,  o);
                ss += __shfl_xor_sync(0xffffffffu, ss, o);
            }
            const float mu   = s * (1.f / EMB);
            const float rstd = rsqrtf(ss * (1.f / EMB) - mu * mu + 1e-5f);
            uint4 q;
            q.x = f2tf((xv.x - mu) * rstd * g1v.x + b1v.x);
            q.y = f2tf((xv.y - mu) * rstd * g1v.y + b1v.y);
            q.z = f2tf((xv.z - mu) * rstd * g1v.z + b1v.z);
            q.w = f2tf((xv.w - mu) * rstd * g1v.w + b1v.w);
            *(uint4*)(Xs + lr * XS_STRIDE + lane * 4) = q;
        }
        __syncthreads();

        // ---- mainloop: 2 rowgroups x 4 nt, B-frags shared across rowgroups
        float acc[2][4][4];
        #pragma unroll
        for (int rg = 0; rg < 2; ++rg)
            #pragma unroll
            for (int nt = 0; nt < 4; ++nt)
                #pragma unroll
                for (int j = 0; j < 4; ++j) acc[rg][nt][j] = 0.f;

        #pragma unroll
        for (int kt = 0; kt < 16; ++kt) {
            uint32_t a[2][4];
            #pragma unroll
            for (int rg = 0; rg < 2; ++rg) {
                const uint32_t* xl = Xs + (rbase + rg * 16 + gq) * XS_STRIDE + kt * 8;
                const uint32_t* xh = Xs + (rbase + rg * 16 + gq + 8) * XS_STRIDE + kt * 8;
                a[rg][0] = xl[tig];
                a[rg][1] = xh[tig];
                a[rg][2] = xl[tig + 4];
                a[rg][3] = xh[tig + 4];
            }
            const uint32_t* wrow = Wp + (kt * 4 + tig) * WP_STRIDE + 2 * cbase;
            uint2 bfr[4];
            #pragma unroll
            for (int nt = 0; nt < 4; ++nt)
                bfr[nt] = *(const uint2*)(wrow + 2 * (nt * 8 + gq));
            #pragma unroll
            for (int rg = 0; rg < 2; ++rg)
                #pragma unroll
                for (int nt = 0; nt < 4; ++nt)
                    mma8(acc[rg][nt][0], acc[rg][nt][1], acc[rg][nt][2], acc[rg][nt][3],
                         a[rg][0], a[rg][1], a[rg][2], a[rg][3], bfr[nt].x, bfr[nt].y);
        }

        // ---- epilogue: +bias, per-row partial stats (32-col partials) ----
        float sl[2] = {0.f, 0.f}, ssl[2] = {0.f, 0.f};
        float sh[2] = {0.f, 0.f}, ssh[2] = {0.f, 0.f};
        #pragma unroll
        for (int rg = 0; rg < 2; ++rg)
            #pragma unroll
            for (int nt = 0; nt < 4; ++nt) {
                const int col = cbase + nt * 8 + 2 * tig;
                const float2 bjv = *(const float2*)(bj + col);
                acc[rg][nt][0] += bjv.x; acc[rg][nt][1] += bjv.y;
                acc[rg][nt][2] += bjv.x; acc[rg][nt][3] += bjv.y;
                sl[rg]  += acc[rg][nt][0] + acc[rg][nt][1];
                ssl[rg] += acc[rg][nt][0] * acc[rg][nt][0] + acc[rg][nt][1] * acc[rg][nt][1];
                sh[rg]  += acc[rg][nt][2] + acc[rg][nt][3];
                ssh[rg] += acc[rg][nt][2] * acc[rg][nt][2] + acc[rg][nt][3] * acc[rg][nt][3];
            }
        #pragma unroll
        for (int o = 1; o < 4; o <<= 1) {
            #pragma unroll
            for (int rg = 0; rg < 2; ++rg) {
                sl[rg]  += __shfl_xor_sync(0xffffffffu, sl[rg],  o);
                ssl[rg] += __shfl_xor_sync(0xffffffffu, ssl[rg], o);
                sh[rg]  += __shfl_xor_sync(0xffffffffu, sh[rg],  o);
                ssh[rg] += __shfl_xor_sync(0xffffffffu, ssh[rg], o);
            }
        }
        if (tig == 0) {
            #pragma unroll
            for (int rg = 0; rg < 2; ++rg) {
                sP [rbase + rg * 16 + gq][wc]     = sl[rg];
                ssP[rbase + rg * 16 + gq][wc]     = ssl[rg];
                sP [rbase + rg * 16 + gq + 8][wc] = sh[rg];
                ssP[rbase + rg * 16 + gq + 8][wc] = ssh[rg];
            }
        }
        __syncthreads();

        // each thread scatters 2 rows (one per rowgroup), parity-selected
        #pragma unroll
        for (int rg = 0; rg < 2; ++rg) {
            const int row = rbase + rg * 16 + (odd ? gq + 8 : gq);
            const float4 sp  = *(const float4*)&sP [row][0];
            const float4 ssp = *(const float4*)&ssP[row][0];
            const float st  = sp.x + sp.y + sp.z + sp.w;
            const float sst = ssp.x + ssp.y + ssp.z + ssp.w;
            const float mu   = st * (1.f / EMB);
            const float rstd = rsqrtf(sst * (1.f / EMB) - mu * mu + 1e-5f);
            const int seg = segs[row];
            float* bse = agg + (size_t)(seg < 0 ? 0 : seg) * EMB;

            #pragma unroll
            for (int nt = 0; nt < 4; ++nt) {
                const float l0 = acc[rg][nt][0], l1 = acc[rg][nt][1];
                const float h0 = acc[rg][nt][2], h1 = acc[rg][nt][3];
                const float p0 = __shfl_xor_sync(0xffffffffu, odd ? l0 : h0, 1);
                const float p1 = __shfl_xor_sync(0xffffffffu, odd ? l1 : h1, 1);
                float v0, v1, v2, v3;
                if (!odd) { v0 = l0; v1 = l1; v2 = p0; v3 = p1; }
                else      { v0 = p0; v1 = p1; v2 = h0; v3 = h1; }
                const int col4 = cbase + nt * 8 + (tig >> 1) * 4;
                const float4 gg  = *(const float4*)(g2 + col4);
                const float4 b2v = *(const float4*)(b2 + col4);
                v0 = (v0 - mu) * rstd * gg.x + b2v.x;
                v1 = (v1 - mu) * rstd * gg.y + b2v.y;
                v2 = (v2 - mu) * rstd * gg.z + b2v.z;
                v3 = (v3 - mu) * rstd * gg.w + b2v.w;
                if (seg >= 0) red_v4(bse + col4, v0, v1, v2, v3);
            }
        }
    }
}

// =====================================================================
// merge (tf32, persistent)
// =====================================================================
__global__ __launch_bounds__(256, 1)
void merge_tf32(const float* __restrict__ h, const float* __restrict__ agg,
                const float* __restrict__ Wm, const float* __restrict__ bm,
                const float* __restrict__ gm, const float* __restrict__ bmln,
                float* __restrict__ dst, int N)
{
    extern __shared__ uint32_t smu[];
    uint32_t* Wp = smu;
    uint32_t* Xs = smu + 128 * WP_STRIDE;
    float*    Xf = (float*)Xs;
    __shared__ float sP[64][2], ssP[64][2];

    const int tid  = threadIdx.x;
    const int lane = tid & 31;
    const int warp = tid >> 5;
    const int gq   = lane >> 2;
    const int tig  = lane & 3;
    const int r0   = (warp >> 1) * 16;
    const int ch   = warp & 1;

    stage_W_tf32<256>(Wm, Wp, tid, 256);

    const int nTiles = (N + 63) >> 6;
    for (int tile = blockIdx.x; tile < nTiles; tile += gridDim.x) {
        const int row0 = tile * 64;
        __syncthreads();

        #pragma unroll
        for (int r = 0; r < 8; ++r) {
            const int lr  = warp * 8 + r;
            const int row = row0 + lr;
            float4 hv = make_float4(0.f, 0.f, 0.f, 0.f);
            float4 av = make_float4(0.f, 0.f, 0.f, 0.f);
            if (row < N) {
                hv = ((const float4*)(h + (size_t)row * EMB))[lane];
                av = __ldcs(((const float4*)(agg + (size_t)row * EMB)) + lane);
            }
            uint4 qh, qa;
            qh.x = f2tf(hv.x); qh.y = f2tf(hv.y); qh.z = f2tf(hv.z); qh.w = f2tf(hv.w);
            qa.x = f2tf(av.x); qa.y = f2tf(av.y); qa.z = f2tf(av.z); qa.w = f2tf(av.w);
            *(uint4*)(Xs + lr * XS2_STRIDE + lane * 4)       = qh;
            *(uint4*)(Xs + lr * XS2_STRIDE + EMB + lane * 4) = qa;
        }
        __syncthreads();

        float acc[8][4];
        #pragma unroll
        for (int i = 0; i < 8; ++i)
            #pragma unroll
            for (int j = 0; j < 4; ++j) acc[i][j] = 0.f;

        mma_mainloop_half<32, XS2_STRIDE>(Xs, Wp, r0, gq, tig, ch, acc);

        float s_lo = 0.f, ss_lo = 0.f, s_hi = 0.f, ss_hi = 0.f;
        #pragma unroll
        for (int nt = 0; nt < 8; ++nt) {
            const int col = ch * 64 + nt * 8 + 2 * tig;
            const float2 bmv = *(const float2*)(bm + col);
            acc[nt][0] = fmaxf(acc[nt][0] + bmv.x, 0.f);
            acc[nt][1] = fmaxf(acc[nt][1] + bmv.y, 0.f);
            acc[nt][2] = fmaxf(acc[nt][2] + bmv.x, 0.f);
            acc[nt][3] = fmaxf(acc[nt][3] + bmv.y, 0.f);
            s_lo  += acc[nt][0] + acc[nt][1];
            ss_lo += acc[nt][0] * acc[nt][0] + acc[nt][1] * acc[nt][1];
            s_hi  += acc[nt][2] + acc[nt][3];
            ss_hi += acc[nt][2] * acc[nt][2] + acc[nt][3] * acc[nt][3];
        }
        #pragma unroll
        for (int o = 1; o < 4; o <<= 1) {
            s_lo  += __shfl_xor_sync(0xffffffffu, s_lo,  o);
            ss_lo += __shfl_xor_sync(0xffffffffu, ss_lo, o);
            s_hi  += __shfl_xor_sync(0xffffffffu, s_hi,  o);
            ss_hi += __shfl_xor_sync(0xffffffffu, ss_hi, o);
        }
        if (tig == 0) {
            sP [r0 + gq][ch]     = s_lo;  ssP[r0 + gq][ch]     = ss_lo;
            sP [r0 + gq + 8][ch] = s_hi;  ssP[r0 + gq + 8][ch] = ss_hi;
        }
        __syncthreads();

        const float st_lo  = sP [r0 + gq][0]     + sP [r0 + gq][1];
        const float sst_lo = ssP[r0 + gq][0]     + ssP[r0 + gq][1];
        const float st_hi  = sP [r0 + gq + 8][0] + sP [r0 + gq + 8][1];
        const float sst_hi = ssP[r0 + gq + 8][0] + ssP[r0 + gq + 8][1];
        const float mu_lo   = st_lo * (1.f / EMB);
        const float rstd_lo = rsqrtf(sst_lo * (1.f / EMB) - mu_lo * mu_lo + 1e-5f);
        const float mu_hi   = st_hi * (1.f / EMB);
        const float rstd_hi = rsqrtf(sst_hi * (1.f / EMB) - mu_hi * mu_hi + 1e-5f);

        #pragma unroll
        for (int nt = 0; nt < 8; ++nt) {
            const int col = ch * 64 + nt * 8 + 2 * tig;
            const float2 gg = *(const float2*)(gm + col);
            const float2 bb = *(const float2*)(bmln + col);
            float* rl = Xf + (r0 + gq)     * XS2_STRIDE + EMB + col;
            float* rh = Xf + (r0 + gq + 8) * XS2_STRIDE + EMB + col;
            rl[0] = (acc[nt][0] - mu_lo) * rstd_lo * gg.x + bb.x;
            rl[1] = (acc[nt][1] - mu_lo) * rstd_lo * gg.y + bb.y;
            rh[0] = (acc[nt][2] - mu_hi) * rstd_hi * gg.x + bb.x;
            rh[1] = (acc[nt][3] - mu_hi) * rstd_hi * gg.y + bb.y;
        }
        __syncthreads();

        #pragma unroll
        for (int r = 0; r < 8; ++r) {
            const int lr  = warp * 8 + r;
            const int row = row0 + lr;
            if (row < N) {
                const float4 hv = ((const float4*)(h + (size_t)row * EMB))[lane];
                const float4 ov = ((const float4*)(Xf + lr * XS2_STRIDE + EMB))[lane];
                float4 o;
                o.x = hv.x + ov.x; o.y = hv.y + ov.y;
                o.z = hv.z + ov.z; o.w = hv.w + ov.w;
                ((float4*)(dst + (size_t)row * EMB))[lane] = o;
            }
        }
    }
}

// =====================================================================
// host
// =====================================================================
extern "C" void kernel_launch(void* const* d_in, const int* in_sizes, int n_in,
                              void* d_out, int out_size)
{
    const float* variable_emb   = (const float*)d_in[0];
    const float* edge_emb       = (const float*)d_in[1];
    const float* constraint_emb = (const float*)d_in[2];
    const int*   e_u            = (const int*)  d_in[3];
    const int*   e_v            = (const int*)  d_in[4];
    const float* W_left   = (const float*)d_in[5];
    const float* b_left   = (const float*)d_in[6];
    const float* W_edge   = (const float*)d_in[7];
    const float* W_right  = (const float*)d_in[8];
    const float* W_join   = (const float*)d_in[9];
    const float* b_join   = (const float*)d_in[10];
    const float* W_merge  = (const float*)d_in[11];
    const float* b_merge  = (const float*)d_in[12];
    const float* g_var    = (const float*)d_in[13];
    const float* b_var    = (const float*)d_in[14];
    const float* g_edge   = (const float*)d_in[15];
    const float* b_edge   = (const float*)d_in[16];
    const float* g_con    = (const float*)d_in[17];
    const float* b_con    = (const float*)d_in[18];
    const float* g_join_ln  = (const float*)d_in[19];
    const float* b_join_ln  = (const float*)d_in[20];
    const float* g_joint    = (const float*)d_in[21];
    const float* b_joint    = (const float*)d_in[22];
    const float* g_merge    = (const float*)d_in[23];
    const float* b_merge_ln = (const float*)d_in[24];

    float* out_var = (float*)d_out;
    float* out_con = (float*)d_out + (size_t)NUv * EMB;

    float *vt, *et, *ct, *agg;
    cudaGetSymbolAddress((void**)&vt,  g_vt);
    cudaGetSymbolAddress((void**)&et,  g_et);
    cudaGetSymbolAddress((void**)&ct,  g_ct);
    cudaGetSymbolAddress((void**)&agg, g_agg);

    const int SM_MMA   = (64 * WP_STRIDE + 64 * XS_STRIDE) * 4;
    const int SM_MERGE = (128 * WP_STRIDE + 64 * XS2_STRIDE) * 4;

    cudaFuncSetAttribute(ln_gemm_tf32,   cudaFuncAttributeMaxDynamicSharedMemorySize, SM_MMA);
    cudaFuncSetAttribute(edge_join_tf32, cudaFuncAttributeMaxDynamicSharedMemorySize, SM_MMA);
    cudaFuncSetAttribute(merge_tf32,     cudaFuncAttributeMaxDynamicSharedMemorySize, SM_MERGE);

    const dim3 blk(256);

    // shared pre-transforms (vt and et identical in both passes)
    ln_gemm_tf32<<<GRID_MMA, blk, SM_MMA>>>(variable_emb, W_left, b_left, g_var, b_var, vt, NUv, 0);
    ln_gemm_tf32<<<GRID_MMA, blk, SM_MMA>>>(edge_emb, W_edge, nullptr, g_edge, b_edge, et, NEv, 1);
    ln_gemm_tf32<<<GRID_MMA, blk, SM_MMA>>>(constraint_emb, W_right, nullptr, g_con, b_con, ct, NVv, 0);

    // ---------------- pass 1: var -> con ----------------
    cudaMemsetAsync(agg, 0, (size_t)NVv * EMB * sizeof(float), 0);
    edge_join_tf32<<<GRID_MMA, blk, SM_MMA>>>(vt, et, ct, e_u, e_v, W_join, b_join,
                                              g_join_ln, b_join_ln, g_joint, b_joint,
                                              agg, /*seg_by_ev=*/1, NEv);
    merge_tf32<<<GRID_MERGE, blk, SM_MERGE>>>(ct, agg, W_merge, b_merge, g_merge, b_merge_ln,
                                              out_con, NVv);

    // ---------------- pass 2: con -> var ----------------
    ln_gemm_tf32<<<GRID_MMA, blk, SM_MMA>>>(out_con, W_right, nullptr, g_con, b_con, ct, NVv, 0);
    cudaMemsetAsync(agg, 0, (size_t)NUv * EMB * sizeof(float), 0);
    edge_join_tf32<<<GRID_MMA, blk, SM_MMA>>>(vt, et, ct, e_u, e_v, W_join, b_join,
                                              g_join_ln, b_join_ln, g_joint, b_joint,
                                              agg, /*seg_by_ev=*/0, NEv);
    merge_tf32<<<GRID_MERGE, blk, SM_MERGE>>>(vt, agg, W_merge, b_merge, g_merge, b_merge_ln,
                                              out_var, NUv);
}